// round 3
// baseline (speedup 1.0000x reference)
#include <cuda_runtime.h>
#include <cstdint>

// RoiAlign 3D (crop_and_resize, trilinear), shapes fixed:
//   features: [B=4, C=128, H=64, W=64, T=64] fp32
//   rois:     [R=512, 7]  (y0,x0,z0,y1,x1,z1, batch_idx) in [0,64] coords
//   out:      [R=512, C=128, 7, 7, 7] fp32
//
// Strategy: one block per (roi, channel). 21 threads precompute per-axis
// (i0, i1, w); 343 threads each produce one output point via 8 __ldg gathers.
// Block working set <= ~17KB -> L1 dedups repeated corners; writes coalesced.

#define RA_C   128
#define RA_DIM 64
#define RA_P   7
#define RA_PTS (RA_P * RA_P * RA_P)   // 343

__global__ __launch_bounds__(352) void roi_align_kernel(
    const float* __restrict__ feat,
    const float* __restrict__ rois,
    float* __restrict__ out)
{
    const int c = blockIdx.x;   // channel
    const int r = blockIdx.y;   // roi

    __shared__ int   s_i0[21];
    __shared__ int   s_i1[21];
    __shared__ float s_w[21];
    __shared__ int   s_b;

    const int tid = threadIdx.x;
    if (tid == 0) {
        s_b = (int)__ldg(&rois[r * 7 + 6]);
    }
    if (tid < 21) {
        const int axis = tid / 7;     // 0=y, 1=x, 2=z
        const int p    = tid % 7;
        const float lo = __ldg(&rois[r * 7 + axis])     * (1.0f / 64.0f);
        const float hi = __ldg(&rois[r * 7 + 3 + axis]) * (1.0f / 64.0f);
        // grid: lo*(dim-1) + (p/(P-1)) * (hi-lo)*(dim-1)
        const float step = (float)p / 6.0f;
        const float cc = lo * 63.0f + step * (hi - lo) * 63.0f;
        const float c0 = floorf(cc);
        const float w  = cc - c0;
        int i0 = (int)c0;
        int i1 = i0 + 1;
        i0 = min(max(i0, 0), RA_DIM - 1);
        i1 = min(max(i1, 0), RA_DIM - 1);
        s_i0[tid] = i0;
        s_i1[tid] = i1;
        s_w[tid]  = w;
    }
    __syncthreads();

    if (tid >= RA_PTS) return;

    const int py  = tid / 49;
    const int rem = tid - py * 49;
    const int px  = rem / 7;
    const int pz  = rem - px * 7;

    const int   y0 = s_i0[py],     y1 = s_i1[py];
    const float wy = s_w[py];
    const int   x0 = s_i0[7 + px], x1 = s_i1[7 + px];
    const float wx = s_w[7 + px];
    const int   z0 = s_i0[14 + pz], z1 = s_i1[14 + pz];
    const float wz = s_w[14 + pz];

    // base for (batch, channel): stride 64^3 = 1<<18 floats
    const float* fb = feat + ((size_t)(s_b * RA_C + c) << 18);

    // addr(y,x,z) = (y<<12) + (x<<6) + z
    const int ry0x0 = (y0 << 12) + (x0 << 6);
    const int ry0x1 = (y0 << 12) + (x1 << 6);
    const int ry1x0 = (y1 << 12) + (x0 << 6);
    const int ry1x1 = (y1 << 12) + (x1 << 6);

    const float f000 = __ldg(fb + ry0x0 + z0);
    const float f001 = __ldg(fb + ry0x0 + z1);
    const float f010 = __ldg(fb + ry0x1 + z0);
    const float f011 = __ldg(fb + ry0x1 + z1);
    const float f100 = __ldg(fb + ry1x0 + z0);
    const float f101 = __ldg(fb + ry1x0 + z1);
    const float f110 = __ldg(fb + ry1x1 + z0);
    const float f111 = __ldg(fb + ry1x1 + z1);

    const float iz = 1.0f - wz;
    const float ix = 1.0f - wx;
    const float iy = 1.0f - wy;

    const float v00 = iz * f000 + wz * f001;
    const float v01 = iz * f010 + wz * f011;
    const float v10 = iz * f100 + wz * f101;
    const float v11 = iz * f110 + wz * f111;

    const float v0 = ix * v00 + wx * v01;
    const float v1 = ix * v10 + wx * v11;

    const float v = iy * v0 + wy * v1;

    out[((size_t)(r * RA_C + c)) * RA_PTS + tid] = v;
}

extern "C" void kernel_launch(void* const* d_in, const int* in_sizes, int n_in,
                              void* d_out, int out_size)
{
    const float* feat = (const float*)d_in[0];
    const float* rois = (const float*)d_in[1];
    float* out = (float*)d_out;

    dim3 grid(RA_C, 512);
    roi_align_kernel<<<grid, 352>>>(feat, rois, out);
}

// round 4
// speedup vs baseline: 1.3645x; 1.3645x over previous
#include <cuda_runtime.h>
#include <cstdint>

// RoiAlign 3D (crop_and_resize, trilinear), shapes fixed:
//   features: [B=4, C=128, H=64, W=64, T=64] fp32
//   rois:     [R=512, 7]  (y0,x0,z0,y1,x1,z1, batch_idx) in [0,64] coords
//   out:      [R=512, C=128, 7, 7, 7] fp32
//
// R3: 247.9us, DRAM=77% @6.1TB/s -> bandwidth-bound; reads were 1.42GB
// (no cross-roi dedup: grid was channel-fast, so concurrent blocks shared
// nothing). R4: grid transposed to roi-fast -> one wave = all 512 rois at
// ONE channel; per-wave L2 working set <= ~4MB, overlapping rois hit L2.

#define RA_C   128
#define RA_DIM 64
#define RA_P   7
#define RA_PTS (RA_P * RA_P * RA_P)   // 343

__global__ __launch_bounds__(352) void roi_align_kernel(
    const float* __restrict__ feat,
    const float* __restrict__ rois,
    float* __restrict__ out)
{
    const int r = blockIdx.x;   // roi   (fast dim: all rois of a channel co-resident)
    const int c = blockIdx.y;   // channel

    __shared__ int   s_i0[21];
    __shared__ int   s_i1[21];
    __shared__ float s_w[21];
    __shared__ int   s_b;

    const int tid = threadIdx.x;
    if (tid == 0) {
        s_b = (int)__ldg(&rois[r * 7 + 6]);
    }
    if (tid < 21) {
        const int axis = tid / 7;     // 0=y, 1=x, 2=z
        const int p    = tid % 7;
        const float lo = __ldg(&rois[r * 7 + axis])     * (1.0f / 64.0f);
        const float hi = __ldg(&rois[r * 7 + 3 + axis]) * (1.0f / 64.0f);
        // grid: lo*(dim-1) + (p/(P-1)) * (hi-lo)*(dim-1)
        const float step = (float)p / 6.0f;
        const float cc = lo * 63.0f + step * (hi - lo) * 63.0f;
        const float c0 = floorf(cc);
        const float w  = cc - c0;
        int i0 = (int)c0;
        int i1 = i0 + 1;
        i0 = min(max(i0, 0), RA_DIM - 1);
        i1 = min(max(i1, 0), RA_DIM - 1);
        s_i0[tid] = i0;
        s_i1[tid] = i1;
        s_w[tid]  = w;
    }
    __syncthreads();

    if (tid >= RA_PTS) return;

    const int py  = tid / 49;
    const int rem = tid - py * 49;
    const int px  = rem / 7;
    const int pz  = rem - px * 7;

    const int   y0 = s_i0[py],     y1 = s_i1[py];
    const float wy = s_w[py];
    const int   x0 = s_i0[7 + px], x1 = s_i1[7 + px];
    const float wx = s_w[7 + px];
    const int   z0 = s_i0[14 + pz], z1 = s_i1[14 + pz];
    const float wz = s_w[14 + pz];

    // base for (batch, channel): stride 64^3 = 1<<18 floats
    const float* fb = feat + ((size_t)(s_b * RA_C + c) << 18);

    // addr(y,x,z) = (y<<12) + (x<<6) + z
    const int ry0x0 = (y0 << 12) + (x0 << 6);
    const int ry0x1 = (y0 << 12) + (x1 << 6);
    const int ry1x0 = (y1 << 12) + (x0 << 6);
    const int ry1x1 = (y1 << 12) + (x1 << 6);

    const float f000 = __ldg(fb + ry0x0 + z0);
    const float f001 = __ldg(fb + ry0x0 + z1);
    const float f010 = __ldg(fb + ry0x1 + z0);
    const float f011 = __ldg(fb + ry0x1 + z1);
    const float f100 = __ldg(fb + ry1x0 + z0);
    const float f101 = __ldg(fb + ry1x0 + z1);
    const float f110 = __ldg(fb + ry1x1 + z0);
    const float f111 = __ldg(fb + ry1x1 + z1);

    const float iz = 1.0f - wz;
    const float ix = 1.0f - wx;
    const float iy = 1.0f - wy;

    const float v00 = iz * f000 + wz * f001;
    const float v01 = iz * f010 + wz * f011;
    const float v10 = iz * f100 + wz * f101;
    const float v11 = iz * f110 + wz * f111;

    const float v0 = ix * v00 + wx * v01;
    const float v1 = ix * v10 + wx * v11;

    const float v = iy * v0 + wy * v1;

    out[((size_t)(r * RA_C + c)) * RA_PTS + tid] = v;
}

extern "C" void kernel_launch(void* const* d_in, const int* in_sizes, int n_in,
                              void* d_out, int out_size)
{
    const float* feat = (const float*)d_in[0];
    const float* rois = (const float*)d_in[1];
    float* out = (float*)d_out;

    dim3 grid(512, RA_C);   // roi fast, channel slow
    roi_align_kernel<<<grid, 352>>>(feat, rois, out);
}